// round 10
// baseline (speedup 1.0000x reference)
#include <cuda_runtime.h>
#include <cuda_fp16.h>
#include <math.h>

// Problem constants (fixed by reference)
#define B_     32
#define L_     16000
#define CF_    5
#define LN2F   0.69314718055994531f
#define HLN2F  0.34657359027997264f   // 0.5*ln2

// k2 tiling: 56 loci per CTA (even => exact symmetric split). 286 CTAs.
#define LC     56
#define NB     286
#define SROW   33                      // smem row stride (elements)

#define SCALE_JS   4294967296.0f       // 2^32
#define ISCALE_JS  (1.0 / 4294967296.0)
#define SCALE_S    1048576.0f          // 2^20 (ce, r2)
#define ISCALE_S   (1.0 / 1048576.0)

// ---- scratch (device globals, zero-initialized at module load) ----
__device__ float          g_js_part [NB * 1024];   // [cta][pair] coalesced
__device__ float          g_cnt_part[NB * 1024];
__device__ float          g_pred[L_ * 8];          // [locus][group]
__device__ unsigned char  g_altp[L_ * 8];          // alt_cnt | (nonmiss<<4)
__device__ int            g_nm_part[NB * 8];       // [cta][group]
__device__ float          g_ce_part[NB * 32];      // [cta][warp]
__device__ long long      g_js_acc[1024];          // fixed-point per pair
__device__ int            g_cnt_acc[1024];
__device__ long long      g_ce_acc, g_r2_acc;
__device__ unsigned int   g_done;

// ============================================================================
// k2: fused staging + per-warp valid-list compacted, branch-free pairwise JS
// ============================================================================
__global__ void __launch_bounds__(1024) k2_mega(
    const float4* __restrict__ logits4,   // (B, L) float4 (C=4)
    const float4* __restrict__ prob4,
    const float*  __restrict__ ytrue)     // (B, L, 5)
{
    __shared__ uint2          s_p[LC * SROW];   // 4 x fp16 clamped prob
    __shared__ unsigned       s_m[LC * SROW];   // (bf16 h' << 16) | label
    __shared__ unsigned short s_vl[32 * 64];    // [batch][slot]: k*SROW; lo<32, hi>=32
    __shared__ unsigned char  s_vc[32 * 2];     // [batch][lo/hi] valid counts
    __shared__ int            s_nm[8];

    const int tid  = threadIdx.x;
    const int lane = tid & 31;
    const int w    = tid >> 5;
    const int l0   = blockIdx.x * LC;
    const int nloc = min(LC, L_ - l0);     // 56 or 40 (even)
    const int n32  = nloc * 32;
    const int H    = nloc >> 1;

    if (tid < 8) s_nm[tid] = 0;
    __syncthreads();

    // ---- staging: coalesced global loads ----
    float ce_acc = 0.0f;
    for (int e = tid; e < n32; e += 1024) {
        int i  = e / nloc;
        int ll = e - i * nloc;
        size_t gi = (size_t)i * L_ + l0 + ll;

        const float* yt = ytrue + gi * CF_;
        float lf = yt[1] + 2.0f * yt[2] + 3.0f * yt[3] + 4.0f * yt[4];
        int lbl = (int)(lf + 0.5f);

        float4 lg = logits4[gi];
        float m  = fmaxf(fmaxf(lg.x, lg.y), fmaxf(lg.z, lg.w));
        float se = __expf(lg.x - m) + __expf(lg.y - m) +
                   __expf(lg.z - m) + __expf(lg.w - m);
        if (lbl != 4) {
            float sel = (lbl == 0) ? lg.x : (lbl == 1) ? lg.y : (lbl == 2) ? lg.z : lg.w;
            ce_acc += (m + LN2F * __log2f(se)) - sel;
        }

        float4 p = prob4[gi];
        float a = fmaxf(p.x, 1e-7f), b = fmaxf(p.y, 1e-7f);
        float c = fmaxf(p.z, 1e-7f), d = fmaxf(p.w, 1e-7f);
        float hp = a * __log2f(a) + b * __log2f(b) +
                   c * __log2f(c) + d * __log2f(d) + (a + b + c + d);
        unsigned hb = (__float_as_uint(hp) + 0x8000u) & 0xFFFF0000u;

        __half2 p01 = __floats2half2_rn(a, b);
        __half2 p23 = __floats2half2_rn(c, d);
        int idx = ll * SROW + i;
        s_p[idx] = make_uint2(reinterpret_cast<unsigned&>(p01),
                              reinterpret_cast<unsigned&>(p23));
        s_m[idx] = hb | (unsigned)lbl;
    }

#pragma unroll
    for (int o = 16; o > 0; o >>= 1) ce_acc += __shfl_xor_sync(0xFFFFFFFFu, ce_acc, o);
    if (lane == 0) g_ce_part[blockIdx.x * 32 + w] = ce_acc;

    __syncthreads();

    // ---- per-warp valid-locus lists (warp w owns batch w; lane 0 builds) ----
    if (lane == 0) {
        int clo = 0, chi = 0;
        for (int ll = 0; ll < H; ++ll)
            if ((s_m[ll * SROW + w] & 0xFFu) != 4u)
                s_vl[w * 64 + clo++] = (unsigned short)(ll * SROW);
        for (int ll = H; ll < nloc; ++ll)
            if ((s_m[ll * SROW + w] & 0xFFu) != 4u)
                s_vl[w * 64 + 32 + chi++] = (unsigned short)(ll * SROW);
        s_vc[w * 2 + 0] = (unsigned char)clo;
        s_vc[w * 2 + 1] = (unsigned char)chi;
    }

    // ---- r2 group partials from staged smem ----
    if (tid < nloc * 8) {
        int g  = tid & 7;
        int ll = tid >> 3;
        int base = ll * SROW + g * 4;
        float pred = 0.0f;
        int alt = 0, nm = 0;
#pragma unroll
        for (int q = 0; q < 4; ++q) {
            uint2 u = s_p[base + q];
            float2 f01 = __half22float2(reinterpret_cast<__half2&>(u.x));
            float2 f23 = __half22float2(reinterpret_cast<__half2&>(u.y));
            pred += f01.y + f23.x + f23.y;
            int lb = s_m[base + q] & 0xFF;
            alt += (lb >= 1 && lb <= 3);
            nm  |= (lb != 4);
        }
        int l = l0 + ll;
        g_pred[l * 8 + g] = 0.25f * pred;
        g_altp[l * 8 + g] = (unsigned char)(alt | (nm << 4));
        if (nm) atomicAdd(&s_nm[g], 1);
    }
    __syncthreads();
    if (tid < 8) g_nm_part[blockIdx.x * 8 + tid] = s_nm[tid];

    // ---- pairwise JS: branch-free walk of warp-uniform valid list ----
    const int i = w;
    const int j = lane;
    {
        const int seg  = (j < i) ? 1 : 0;          // hi for j<i, lo for j>=i
        const int vbase = i * 64 + seg * 32;
        const int n_it  = s_vc[i * 2 + seg];       // warp-uniform

        float js = 0.0f, cnt = 0.0f;
#pragma unroll 4
        for (int t = 0; t < n_it; ++t) {
            const int row = s_vl[vbase + t];       // broadcast; = k*SROW
            unsigned wi = s_m[row + i];            // broadcast; label != 4
            unsigned wj = s_m[row + j];
            float msk = (((wi ^ wj) & 0xFFu) == 0u) ? 1.0f : 0.0f;
            uint2 ui = s_p[row + i];               // broadcast
            uint2 uj = s_p[row + j];
            __half2 s01 = __hadd2(reinterpret_cast<__half2&>(ui.x),
                                  reinterpret_cast<__half2&>(uj.x));
            __half2 s23 = __hadd2(reinterpret_cast<__half2&>(ui.y),
                                  reinterpret_cast<__half2&>(uj.y));
            float2 f01 = __half22float2(s01);
            float2 f23 = __half22float2(s23);
            float slog2 = f01.x * __log2f(f01.x) + f01.y * __log2f(f01.y) +
                          f23.x * __log2f(f23.x) + f23.y * __log2f(f23.y);
            float hsum = __uint_as_float(wi & 0xFFFF0000u) +
                         __uint_as_float(wj & 0xFFFF0000u);
            js  = fmaf(msk, hsum - slog2, js);     // HLN2F applied in kF
            cnt += msk;
        }

        g_js_part [blockIdx.x * 1024 + tid] = js;   // coalesced
        g_cnt_part[blockIdx.x * 1024 + tid] = cnt;
    }
}

// ============================================================================
// kF: 32 blocks x 1024 (proven R7 version). Deterministic fixed-point atomics;
//     last-done block finalizes + resets.
// ============================================================================
__global__ void __launch_bounds__(1024) kF(const float* __restrict__ yevo,
                                           float* __restrict__ out)
{
    const int tid  = threadIdx.x;
    const int w    = tid >> 5;
    const int lane = tid & 31;
    const int bid  = blockIdx.x;

    __shared__ int   s_nm[8];
    __shared__ float s_red[2][32];
    __shared__ int   s_last;

    // (a) pair partials: rows bid, bid+32, ... (coalesced), one atomic per pair
    {
        float js = 0.0f, cnt = 0.0f;
        for (int r = bid; r < NB; r += 32) {
            js  += g_js_part [r * 1024 + tid];
            cnt += g_cnt_part[r * 1024 + tid];
        }
        atomicAdd((unsigned long long*)&g_js_acc[tid],
                  (unsigned long long)(long long)(js * SCALE_JS));
        atomicAdd(&g_cnt_acc[tid], (int)cnt);        // counts are exact floats
    }

    // (b) nm totals (each block computes its own copy; cheap)
    if (w < 8) {
        int nm = 0;
        for (int b = lane; b < NB; b += 32) nm += g_nm_part[b * 8 + w];
#pragma unroll
        for (int o = 16; o > 0; o >>= 1) nm += __shfl_xor_sync(0xFFFFFFFFu, nm, o);
        if (lane == 0) s_nm[w] = nm;
    }
    __syncthreads();

    // (c) r2 slice over (locus, group)
    float r2acc = 0.0f;
#pragma unroll 4
    for (int idx = bid * 1024 + tid; idx < L_ * 8; idx += 32768) {
        int g = idx & 7;
        float cntg = fmaxf(4.0f * (float)s_nm[g], 1.0f);
        unsigned char pk = g_altp[idx];
        float alt = (float)(pk & 15);
        bool nonmiss = (pk & 16) != 0;
        float af2 = nonmiss ? (alt / cntg) : 0.5f;
        if (nonmiss && af2 != 0.0f && af2 != 1.0f) {
            float den = fmaxf(af2 * (1.0f - af2), 0.01f);
            float dd  = g_pred[idx] - af2;
            r2acc += dd * dd / den;
        }
    }

    // (d) CE slice
    float ceacc = 0.0f;
    for (int idx = bid * 1024 + tid; idx < NB * 32; idx += 32768)
        ceacc += g_ce_part[idx];

    // block-reduce r2 + ce -> one atomic each
#pragma unroll
    for (int o = 16; o > 0; o >>= 1) {
        r2acc += __shfl_xor_sync(0xFFFFFFFFu, r2acc, o);
        ceacc += __shfl_xor_sync(0xFFFFFFFFu, ceacc, o);
    }
    if (lane == 0) { s_red[0][w] = r2acc; s_red[1][w] = ceacc; }
    __syncthreads();
    if (tid == 0) {
        float r2 = 0.0f, ce = 0.0f;
#pragma unroll
        for (int k = 0; k < 32; ++k) { r2 += s_red[0][k]; ce += s_red[1][k]; }
        atomicAdd((unsigned long long*)&g_r2_acc,
                  (unsigned long long)(long long)(r2 * SCALE_S));
        atomicAdd((unsigned long long*)&g_ce_acc,
                  (unsigned long long)(long long)(ce * SCALE_S));
    }

    // completion protocol
    __threadfence();
    __syncthreads();
    if (tid == 0) s_last = (atomicAdd(&g_done, 1u) == 31u);
    __syncthreads();
    if (!s_last) return;
    __threadfence();

    // ---- last block: evo combine + output + reset ----
    __shared__ float s_j[1024];
    __shared__ int   s_c[1024];
    s_j[tid] = (float)((double)g_js_acc[tid] * ISCALE_JS);
    s_c[tid] = g_cnt_acc[tid];
    __syncthreads();
    const int tT = lane * 32 + w;                    // transpose
    float jsv = HLN2F * (s_j[tid] + s_j[tT]) /
                fmaxf((float)(s_c[tid] + s_c[tT]), 1.0f);
    float wgt = __expf(-yevo[tid]);
    float rs = wgt;
#pragma unroll
    for (int o = 16; o > 0; o >>= 1) rs += __shfl_xor_sync(0xFFFFFFFFu, rs, o);
    float term = (wgt / (rs + 1e-8f)) * jsv;
#pragma unroll
    for (int o = 16; o > 0; o >>= 1) term += __shfl_xor_sync(0xFFFFFFFFu, term, o);
    __syncthreads();
    if (lane == 0) s_red[0][w] = term;
    __syncthreads();
    if (tid == 0) {
        float evo = 0.0f;
#pragma unroll
        for (int k = 0; k < 32; ++k) evo += s_red[0][k];
        float ce = (float)((double)g_ce_acc * ISCALE_S);
        float r2 = (float)((double)g_r2_acc * ISCALE_S);
        if (!isfinite(evo)) evo = 0.0f;
        out[0] = ce - 0.125f * r2 + evo;   // r2_loss = -sum*GS/B
    }

    // reset accumulators for the next graph replay
    __syncthreads();
    g_js_acc[tid] = 0ll;
    g_cnt_acc[tid] = 0;
    if (tid == 0) { g_ce_acc = 0ll; g_r2_acc = 0ll; g_done = 0u; }
}

extern "C" void kernel_launch(void* const* d_in, const int* in_sizes, int n_in,
                              void* d_out, int out_size)
{
    const float* logits = (const float*)d_in[0];
    const float* prob   = (const float*)d_in[1];
    const float* ytrue  = (const float*)d_in[2];
    const float* yevo   = (const float*)d_in[3];

    k2_mega<<<NB, 1024>>>((const float4*)logits, (const float4*)prob, ytrue);
    kF     <<<32, 1024>>>(yevo, (float*)d_out);
}

// round 11
// speedup vs baseline: 1.1738x; 1.1738x over previous
#include <cuda_runtime.h>
#include <math.h>

// Problem constants (fixed by reference)
#define B_     32
#define L_     16000
#define CF_    5
#define LN2F   0.69314718055994531f
#define HLN2F  0.34657359027997264f   // 0.5*ln2

// k2 tiling: 56 loci per CTA (even => exact symmetric split). 286 CTAs.
#define LC     56
#define NB     286
#define SROW   33                      // smem row stride (elements)

#define SCALE_JS   4294967296.0f       // 2^32
#define ISCALE_JS  (1.0 / 4294967296.0)
#define SCALE_S    1048576.0f          // 2^20 (ce, r2)
#define ISCALE_S   (1.0 / 1048576.0)

// ---- scratch (device globals, zero-initialized at module load) ----
__device__ float          g_js_part [NB * 1024];   // [cta][pair] coalesced
__device__ float          g_cnt_part[NB * 1024];
__device__ float          g_pred[L_ * 8];          // [locus][group]
__device__ unsigned char  g_altp[L_ * 8];          // alt_cnt | (nonmiss<<4)
__device__ int            g_nm_part[NB * 8];       // [cta][group]
__device__ float          g_ce_part[NB * 32];      // [cta][warp]
__device__ long long      g_js_acc[1024];          // fixed-point per pair
__device__ int            g_cnt_acc[1024];
__device__ long long      g_ce_acc, g_r2_acc;
__device__ unsigned int   g_done;

// ============================================================================
// k2: fused staging (labels, CE, h', f32 probs) + symmetric pairwise JS
// (R7 structure; probs stored as float4 to remove half conversions)
// ============================================================================
__global__ void __launch_bounds__(1024) k2_mega(
    const float4* __restrict__ logits4,   // (B, L) float4 (C=4)
    const float4* __restrict__ prob4,
    const float*  __restrict__ ytrue)     // (B, L, 5)
{
    __shared__ float4   s_p[LC * SROW];   // clamped prob (f32)
    __shared__ unsigned s_m[LC * SROW];   // (bf16 h' << 16) | label
    __shared__ int      s_nm[8];

    const int tid  = threadIdx.x;
    const int lane = tid & 31;
    const int l0   = blockIdx.x * LC;
    const int nloc = min(LC, L_ - l0);     // 56 or 40 (even)
    const int n32  = nloc * 32;

    if (tid < 8) s_nm[tid] = 0;
    __syncthreads();

    // ---- staging: coalesced global loads ----
    float ce_acc = 0.0f;
    for (int e = tid; e < n32; e += 1024) {
        int i  = e / nloc;
        int ll = e - i * nloc;
        size_t gi = (size_t)i * L_ + l0 + ll;

        const float* yt = ytrue + gi * CF_;
        float lf = yt[1] + 2.0f * yt[2] + 3.0f * yt[3] + 4.0f * yt[4];
        int lbl = (int)(lf + 0.5f);

        float4 lg = logits4[gi];
        float m  = fmaxf(fmaxf(lg.x, lg.y), fmaxf(lg.z, lg.w));
        float se = __expf(lg.x - m) + __expf(lg.y - m) +
                   __expf(lg.z - m) + __expf(lg.w - m);
        if (lbl != 4) {
            float sel = (lbl == 0) ? lg.x : (lbl == 1) ? lg.y : (lbl == 2) ? lg.z : lg.w;
            ce_acc += (m + LN2F * __log2f(se)) - sel;
        }

        float4 p = prob4[gi];
        float a = fmaxf(p.x, 1e-7f), b = fmaxf(p.y, 1e-7f);
        float c = fmaxf(p.z, 1e-7f), d = fmaxf(p.w, 1e-7f);
        float hp = a * __log2f(a) + b * __log2f(b) +
                   c * __log2f(c) + d * __log2f(d) + (a + b + c + d);
        unsigned hb = (__float_as_uint(hp) + 0x8000u) & 0xFFFF0000u;

        int idx = ll * SROW + i;
        s_p[idx] = make_float4(a, b, c, d);
        s_m[idx] = hb | (unsigned)lbl;
    }

#pragma unroll
    for (int o = 16; o > 0; o >>= 1) ce_acc += __shfl_xor_sync(0xFFFFFFFFu, ce_acc, o);
    if (lane == 0) g_ce_part[blockIdx.x * 32 + (tid >> 5)] = ce_acc;

    __syncthreads();

    // ---- r2 group partials from staged smem ----
    if (tid < nloc * 8) {
        int g  = tid & 7;
        int ll = tid >> 3;
        int base = ll * SROW + g * 4;
        float pred = 0.0f;
        int alt = 0, nm = 0;
#pragma unroll
        for (int q = 0; q < 4; ++q) {
            float4 p = s_p[base + q];
            pred += p.y + p.z + p.w;
            int lb = s_m[base + q] & 0xFF;
            alt += (lb >= 1 && lb <= 3);
            nm  |= (lb != 4);
        }
        int l = l0 + ll;
        g_pred[l * 8 + g] = 0.25f * pred;
        g_altp[l * 8 + g] = (unsigned char)(alt | (nm << 4));
        if (nm) atomicAdd(&s_nm[g], 1);
    }
    __syncthreads();
    if (tid < 8) g_nm_part[blockIdx.x * 8 + tid] = s_nm[tid];

    // ---- symmetric pairwise JS: (i,j) j>=i does [0,H); j<i does [H,nloc) ----
    const int i = tid >> 5;
    const int j = lane;
    const int H = nloc >> 1;
    const int start = (j < i) ? H : 0;

    float js = 0.0f;
    int   cnt = 0;
#pragma unroll 2
    for (int k = 0; k < H; ++k) {
        const int row = (start + k) * SROW;
        unsigned wi = s_m[row + i];           // broadcast
        if ((wi & 0xFFu) == 4u) continue;     // warp-uniform skip (20% of loci)
        unsigned wj = s_m[row + j];
        bool act = (((wi ^ wj) & 0xFFu) == 0u);
        float msk = act ? 1.0f : 0.0f;
        float4 pi = s_p[row + i];             // broadcast LDS.128
        float4 pj = s_p[row + j];             // LDS.128
        float s0 = pi.x + pj.x, s1 = pi.y + pj.y;
        float s2 = pi.z + pj.z, s3 = pi.w + pj.w;
        float slog2 = s0 * __log2f(s0) + s1 * __log2f(s1) +
                      s2 * __log2f(s2) + s3 * __log2f(s3);
        float hsum = __uint_as_float(wi & 0xFFFF0000u) +
                     __uint_as_float(wj & 0xFFFF0000u);
        js  = fmaf(msk, hsum - slog2, js);    // HLN2F applied in kF
        cnt += act;
    }

    g_js_part [blockIdx.x * 1024 + tid] = js;        // coalesced
    g_cnt_part[blockIdx.x * 1024 + tid] = (float)cnt;
}

// ============================================================================
// kF: 32 blocks x 1024 (proven R7 version). Deterministic fixed-point atomics;
//     last-done block finalizes + resets.
// ============================================================================
__global__ void __launch_bounds__(1024) kF(const float* __restrict__ yevo,
                                           float* __restrict__ out)
{
    const int tid  = threadIdx.x;
    const int w    = tid >> 5;
    const int lane = tid & 31;
    const int bid  = blockIdx.x;

    __shared__ int   s_nm[8];
    __shared__ float s_red[2][32];
    __shared__ int   s_last;

    // (a) pair partials: rows bid, bid+32, ... (coalesced), one atomic per pair
    {
        float js = 0.0f, cnt = 0.0f;
        for (int r = bid; r < NB; r += 32) {
            js  += g_js_part [r * 1024 + tid];
            cnt += g_cnt_part[r * 1024 + tid];
        }
        atomicAdd((unsigned long long*)&g_js_acc[tid],
                  (unsigned long long)(long long)(js * SCALE_JS));
        atomicAdd(&g_cnt_acc[tid], (int)cnt);        // counts are exact floats
    }

    // (b) nm totals (each block computes its own copy; cheap)
    if (w < 8) {
        int nm = 0;
        for (int b = lane; b < NB; b += 32) nm += g_nm_part[b * 8 + w];
#pragma unroll
        for (int o = 16; o > 0; o >>= 1) nm += __shfl_xor_sync(0xFFFFFFFFu, nm, o);
        if (lane == 0) s_nm[w] = nm;
    }
    __syncthreads();

    // (c) r2 slice over (locus, group)
    float r2acc = 0.0f;
#pragma unroll 4
    for (int idx = bid * 1024 + tid; idx < L_ * 8; idx += 32768) {
        int g = idx & 7;
        float cntg = fmaxf(4.0f * (float)s_nm[g], 1.0f);
        unsigned char pk = g_altp[idx];
        float alt = (float)(pk & 15);
        bool nonmiss = (pk & 16) != 0;
        float af2 = nonmiss ? (alt / cntg) : 0.5f;
        if (nonmiss && af2 != 0.0f && af2 != 1.0f) {
            float den = fmaxf(af2 * (1.0f - af2), 0.01f);
            float dd  = g_pred[idx] - af2;
            r2acc += dd * dd / den;
        }
    }

    // (d) CE slice
    float ceacc = 0.0f;
    for (int idx = bid * 1024 + tid; idx < NB * 32; idx += 32768)
        ceacc += g_ce_part[idx];

    // block-reduce r2 + ce -> one atomic each
#pragma unroll
    for (int o = 16; o > 0; o >>= 1) {
        r2acc += __shfl_xor_sync(0xFFFFFFFFu, r2acc, o);
        ceacc += __shfl_xor_sync(0xFFFFFFFFu, ceacc, o);
    }
    if (lane == 0) { s_red[0][w] = r2acc; s_red[1][w] = ceacc; }
    __syncthreads();
    if (tid == 0) {
        float r2 = 0.0f, ce = 0.0f;
#pragma unroll
        for (int k = 0; k < 32; ++k) { r2 += s_red[0][k]; ce += s_red[1][k]; }
        atomicAdd((unsigned long long*)&g_r2_acc,
                  (unsigned long long)(long long)(r2 * SCALE_S));
        atomicAdd((unsigned long long*)&g_ce_acc,
                  (unsigned long long)(long long)(ce * SCALE_S));
    }

    // completion protocol
    __threadfence();
    __syncthreads();
    if (tid == 0) s_last = (atomicAdd(&g_done, 1u) == 31u);
    __syncthreads();
    if (!s_last) return;
    __threadfence();

    // ---- last block: evo combine + output + reset ----
    __shared__ float s_j[1024];
    __shared__ int   s_c[1024];
    s_j[tid] = (float)((double)g_js_acc[tid] * ISCALE_JS);
    s_c[tid] = g_cnt_acc[tid];
    __syncthreads();
    const int tT = lane * 32 + w;                    // transpose
    float jsv = HLN2F * (s_j[tid] + s_j[tT]) /
                fmaxf((float)(s_c[tid] + s_c[tT]), 1.0f);
    float wgt = __expf(-yevo[tid]);
    float rs = wgt;
#pragma unroll
    for (int o = 16; o > 0; o >>= 1) rs += __shfl_xor_sync(0xFFFFFFFFu, rs, o);
    float term = (wgt / (rs + 1e-8f)) * jsv;
#pragma unroll
    for (int o = 16; o > 0; o >>= 1) term += __shfl_xor_sync(0xFFFFFFFFu, term, o);
    __syncthreads();
    if (lane == 0) s_red[0][w] = term;
    __syncthreads();
    if (tid == 0) {
        float evo = 0.0f;
#pragma unroll
        for (int k = 0; k < 32; ++k) evo += s_red[0][k];
        float ce = (float)((double)g_ce_acc * ISCALE_S);
        float r2 = (float)((double)g_r2_acc * ISCALE_S);
        if (!isfinite(evo)) evo = 0.0f;
        out[0] = ce - 0.125f * r2 + evo;   // r2_loss = -sum*GS/B
    }

    // reset accumulators for the next graph replay
    __syncthreads();
    g_js_acc[tid] = 0ll;
    g_cnt_acc[tid] = 0;
    if (tid == 0) { g_ce_acc = 0ll; g_r2_acc = 0ll; g_done = 0u; }
}

extern "C" void kernel_launch(void* const* d_in, const int* in_sizes, int n_in,
                              void* d_out, int out_size)
{
    const float* logits = (const float*)d_in[0];
    const float* prob   = (const float*)d_in[1];
    const float* ytrue  = (const float*)d_in[2];
    const float* yevo   = (const float*)d_in[3];

    k2_mega<<<NB, 1024>>>((const float4*)logits, (const float4*)prob, ytrue);
    kF     <<<32, 1024>>>(yevo, (float*)d_out);
}

// round 12
// speedup vs baseline: 1.3268x; 1.1303x over previous
#include <cuda_runtime.h>
#include <cuda_fp16.h>
#include <math.h>

// Problem constants (fixed by reference)
#define B_     32
#define L_     16000
#define CF_    5
#define LN2F   0.69314718055994531f
#define HLN2F  0.34657359027997264f   // 0.5*ln2

// Tiling: 64 loci per CTA -> 250 CTAs exactly (16000/64), even symmetric split.
// Co-residency: 250 <= 148 SMs * 2 CTAs (forced by __launch_bounds__(1024,2)).
#define LC     64
#define NB     250
#define SROW   33                      // smem row stride (elements)

#define SCALE_JS   4294967296.0f       // 2^32
#define ISCALE_JS  (1.0 / 4294967296.0)
#define SCALE_S    1048576.0f          // 2^20 (ce, r2)
#define ISCALE_S   (1.0 / 1048576.0)

// ---- scratch (device globals, zero-initialized at module load) ----
__device__ float          g_js_part [NB * 1024];   // [cta][pair] coalesced
__device__ float          g_cnt_part[NB * 1024];
__device__ float          g_pred[L_ * 8];          // [locus][group]
__device__ unsigned char  g_altp[L_ * 8];          // alt_cnt | (nonmiss<<4)
__device__ int            g_nm_tot[8];             // per-group nonmiss totals
__device__ long long      g_js_acc[1024];          // fixed-point per pair
__device__ int            g_cnt_acc[1024];
__device__ long long      g_ce_acc, g_r2_acc;
__device__ unsigned int   g_done, g_done2;

// ============================================================================
// Single persistent kernel: phase 1 = R7's k2 (staging + CE + r2 partials +
// symmetric pairwise JS); grid-wide spin barrier; phase 2 = parallel reduction;
// last-done block finalizes + resets.
// ============================================================================
__global__ void __launch_bounds__(1024, 2) k_fused(
    const float4* __restrict__ logits4,   // (B, L) float4 (C=4)
    const float4* __restrict__ prob4,
    const float*  __restrict__ ytrue,     // (B, L, 5)
    const float*  __restrict__ yevo,      // (B, B)
    float*        __restrict__ out)
{
    __shared__ uint2    s_p[LC * SROW];   // 4 x fp16 clamped prob
    __shared__ unsigned s_m[LC * SROW];   // (bf16 h' << 16) | label
    __shared__ int      s_nm[8];
    __shared__ float    s_red[32];
    __shared__ float    s_j[1024];        // finalize staging
    __shared__ int      s_c[1024];
    __shared__ int      s_last;

    const int tid  = threadIdx.x;
    const int lane = tid & 31;
    const int w    = tid >> 5;
    const int bid  = blockIdx.x;
    const int l0   = bid * LC;

    if (tid < 8) s_nm[tid] = 0;
    __syncthreads();

    // ---- phase 1a: staging (coalesced; lanes walk consecutive loci) ----
    float ce_acc = 0.0f;
#pragma unroll
    for (int q = 0; q < 2; ++q) {
        int e  = q * 1024 + tid;          // 2048 = LC*32 exactly
        int i  = e >> 6;                  // batch
        int ll = e & 63;                  // local locus
        size_t gi = (size_t)i * L_ + l0 + ll;

        const float* yt = ytrue + gi * CF_;
        float lf = yt[1] + 2.0f * yt[2] + 3.0f * yt[3] + 4.0f * yt[4];
        int lbl = (int)(lf + 0.5f);

        float4 lg = logits4[gi];
        float m  = fmaxf(fmaxf(lg.x, lg.y), fmaxf(lg.z, lg.w));
        float se = __expf(lg.x - m) + __expf(lg.y - m) +
                   __expf(lg.z - m) + __expf(lg.w - m);
        if (lbl != 4) {
            float sel = (lbl == 0) ? lg.x : (lbl == 1) ? lg.y : (lbl == 2) ? lg.z : lg.w;
            ce_acc += (m + LN2F * __log2f(se)) - sel;
        }

        float4 p = prob4[gi];
        float a = fmaxf(p.x, 1e-7f), b = fmaxf(p.y, 1e-7f);
        float c = fmaxf(p.z, 1e-7f), d = fmaxf(p.w, 1e-7f);
        float hp = a * __log2f(a) + b * __log2f(b) +
                   c * __log2f(c) + d * __log2f(d) + (a + b + c + d);
        unsigned hb = (__float_as_uint(hp) + 0x8000u) & 0xFFFF0000u;

        __half2 p01 = __floats2half2_rn(a, b);
        __half2 p23 = __floats2half2_rn(c, d);
        int idx = ll * SROW + i;
        s_p[idx] = make_uint2(reinterpret_cast<unsigned&>(p01),
                              reinterpret_cast<unsigned&>(p23));
        s_m[idx] = hb | (unsigned)lbl;
    }

    // CE: warp partials -> CTA sum -> one deterministic fixed-point atomic
#pragma unroll
    for (int o = 16; o > 0; o >>= 1) ce_acc += __shfl_xor_sync(0xFFFFFFFFu, ce_acc, o);
    if (lane == 0) s_red[w] = ce_acc;
    __syncthreads();
    if (tid == 0) {
        float s = 0.0f;
#pragma unroll
        for (int k = 0; k < 32; ++k) s += s_red[k];
        atomicAdd((unsigned long long*)&g_ce_acc,
                  (unsigned long long)(long long)(s * SCALE_S));
    }

    // ---- phase 1b: r2 group partials ----
    if (tid < LC * 8) {
        int g  = tid & 7;
        int ll = tid >> 3;
        int base = ll * SROW + g * 4;
        float pred = 0.0f;
        int alt = 0, nm = 0;
#pragma unroll
        for (int q = 0; q < 4; ++q) {
            uint2 u = s_p[base + q];
            float2 f01 = __half22float2(reinterpret_cast<__half2&>(u.x));
            float2 f23 = __half22float2(reinterpret_cast<__half2&>(u.y));
            pred += f01.y + f23.x + f23.y;
            int lb = s_m[base + q] & 0xFF;
            alt += (lb >= 1 && lb <= 3);
            nm  |= (lb != 4);
        }
        int l = l0 + ll;
        g_pred[l * 8 + g] = 0.25f * pred;
        g_altp[l * 8 + g] = (unsigned char)(alt | (nm << 4));
        if (nm) atomicAdd(&s_nm[g], 1);
    }
    __syncthreads();
    if (tid < 8) atomicAdd(&g_nm_tot[tid], s_nm[tid]);

    // ---- phase 1c: symmetric pairwise JS (R7's proven uniform loop) ----
    const int i = w;
    const int j = lane;
    const int start = (j < i) ? (LC / 2) : 0;

    float js = 0.0f, cnt = 0.0f;
#pragma unroll 2
    for (int k = 0; k < LC / 2; ++k) {
        const int row = (start + k) * SROW;
        unsigned wi = s_m[row + i];           // broadcast
        if ((wi & 0xFFu) == 4u) continue;     // warp-uniform skip (20% of loci)
        unsigned wj = s_m[row + j];
        float msk = (((wi ^ wj) & 0xFFu) == 0u) ? 1.0f : 0.0f;
        uint2 ui = s_p[row + i];              // broadcast
        uint2 uj = s_p[row + j];
        __half2 s01 = __hadd2(reinterpret_cast<__half2&>(ui.x),
                              reinterpret_cast<__half2&>(uj.x));
        __half2 s23 = __hadd2(reinterpret_cast<__half2&>(ui.y),
                              reinterpret_cast<__half2&>(uj.y));
        float2 f01 = __half22float2(s01);
        float2 f23 = __half22float2(s23);
        float slog2 = f01.x * __log2f(f01.x) + f01.y * __log2f(f01.y) +
                      f23.x * __log2f(f23.x) + f23.y * __log2f(f23.y);
        float hsum = __uint_as_float(wi & 0xFFFF0000u) +
                     __uint_as_float(wj & 0xFFFF0000u);
        js  = fmaf(msk, hsum - slog2, js);    // HLN2F applied at finalize
        cnt += msk;
    }

    g_js_part [bid * 1024 + tid] = js;        // coalesced
    g_cnt_part[bid * 1024 + tid] = cnt;

    // ---- grid-wide barrier (all NB CTAs are co-resident by construction) ----
    __threadfence();
    __syncthreads();
    if (tid == 0) {
        atomicAdd(&g_done, 1u);
        while (atomicOr(&g_done, 0u) < NB) __nanosleep(64);
    }
    __syncthreads();
    __threadfence();

    // ---- phase 2: parallel reduction ----
    if (bid < 32) {
        // pair-partial scan (kF's proven shape): rows bid, bid+32, ...
        float pjs = 0.0f, pcnt = 0.0f;
        for (int r = bid; r < NB; r += 32) {
            pjs  += g_js_part [r * 1024 + tid];
            pcnt += g_cnt_part[r * 1024 + tid];
        }
        atomicAdd((unsigned long long*)&g_js_acc[tid],
                  (unsigned long long)(long long)(pjs * SCALE_JS));
        atomicAdd(&g_cnt_acc[tid], (int)pcnt);
    } else if (bid < 157) {
        // r2: one (locus, group) item per thread; 125 blocks cover 128000
        if (tid < 8) s_nm[tid] = g_nm_tot[tid];
        __syncthreads();
        int idx = (bid - 32) * 1024 + tid;
        float r2acc = 0.0f;
        if (idx < L_ * 8) {
            int g = idx & 7;
            float cntg = fmaxf(4.0f * (float)s_nm[g], 1.0f);
            unsigned char pk = g_altp[idx];
            float alt = (float)(pk & 15);
            bool nonmiss = (pk & 16) != 0;
            float af2 = nonmiss ? (alt / cntg) : 0.5f;
            if (nonmiss && af2 != 0.0f && af2 != 1.0f) {
                float den = fmaxf(af2 * (1.0f - af2), 0.01f);
                float dd  = g_pred[idx] - af2;
                r2acc = dd * dd / den;
            }
        }
#pragma unroll
        for (int o = 16; o > 0; o >>= 1) r2acc += __shfl_xor_sync(0xFFFFFFFFu, r2acc, o);
        __syncthreads();                       // s_red free after phase 1
        if (lane == 0) s_red[w] = r2acc;
        __syncthreads();
        if (tid == 0) {
            float r2 = 0.0f;
#pragma unroll
            for (int k = 0; k < 32; ++k) r2 += s_red[k];
            atomicAdd((unsigned long long*)&g_r2_acc,
                      (unsigned long long)(long long)(r2 * SCALE_S));
        }
    }

    // ---- completion counter; last block finalizes ----
    __threadfence();
    __syncthreads();
    if (tid == 0) s_last = (atomicAdd(&g_done2, 1u) == NB - 1);
    __syncthreads();
    if (!s_last) return;
    __threadfence();

    // evo combine: transpose symmetric halves, weights, output
    s_j[tid] = (float)((double)g_js_acc[tid] * ISCALE_JS);
    s_c[tid] = g_cnt_acc[tid];
    __syncthreads();
    const int tT = lane * 32 + w;
    float jsv = HLN2F * (s_j[tid] + s_j[tT]) /
                fmaxf((float)(s_c[tid] + s_c[tT]), 1.0f);
    float wgt = __expf(-yevo[tid]);
    float rs = wgt;
#pragma unroll
    for (int o = 16; o > 0; o >>= 1) rs += __shfl_xor_sync(0xFFFFFFFFu, rs, o);
    float term = (wgt / (rs + 1e-8f)) * jsv;
#pragma unroll
    for (int o = 16; o > 0; o >>= 1) term += __shfl_xor_sync(0xFFFFFFFFu, term, o);
    __syncthreads();
    if (lane == 0) s_red[w] = term;
    __syncthreads();
    if (tid == 0) {
        float evo = 0.0f;
#pragma unroll
        for (int k = 0; k < 32; ++k) evo += s_red[k];
        float ce = (float)((double)g_ce_acc * ISCALE_S);
        float r2 = (float)((double)g_r2_acc * ISCALE_S);
        if (!isfinite(evo)) evo = 0.0f;
        out[0] = ce - 0.125f * r2 + evo;   // r2_loss = -sum*GS/B
    }

    // reset accumulators for the next graph replay
    __syncthreads();
    g_js_acc[tid] = 0ll;
    g_cnt_acc[tid] = 0;
    if (tid < 8) g_nm_tot[tid] = 0;
    if (tid == 0) { g_ce_acc = 0ll; g_r2_acc = 0ll; g_done = 0u; g_done2 = 0u; }
}

extern "C" void kernel_launch(void* const* d_in, const int* in_sizes, int n_in,
                              void* d_out, int out_size)
{
    const float* logits = (const float*)d_in[0];
    const float* prob   = (const float*)d_in[1];
    const float* ytrue  = (const float*)d_in[2];
    const float* yevo   = (const float*)d_in[3];

    k_fused<<<NB, 1024>>>((const float4*)logits, (const float4*)prob,
                          ytrue, yevo, (float*)d_out);
}

// round 13
// speedup vs baseline: 1.3714x; 1.0337x over previous
#include <cuda_runtime.h>
#include <cuda_fp16.h>
#include <math.h>

// Problem constants (fixed by reference)
#define B_     32
#define L_     16000
#define CF_    5
#define LN2F   0.69314718055994531f
#define HLN2F  0.34657359027997264f   // 0.5*ln2

// Tiling: 64 loci per CTA -> 250 CTAs exactly (16000/64), even symmetric split.
// Co-residency: 250 <= 148 SMs * 2 CTAs (forced by __launch_bounds__(1024,2)).
#define LC     64
#define NB     250
#define NR2    125                     // r2 blocks after barrier: 125*1024 = 128000
#define SROW   33                      // smem row stride (elements)

#define SCALE_JS   4294967296.0f       // 2^32
#define ISCALE_JS  (1.0 / 4294967296.0)
#define SCALE_S    1048576.0f          // 2^20 (ce, r2)
#define ISCALE_S   (1.0 / 1048576.0)

// ---- scratch (device globals, zero-initialized at module load) ----
__device__ float          g_pred[L_ * 8];          // [locus][group]
__device__ unsigned char  g_altp[L_ * 8];          // alt_cnt | (nonmiss<<4)
__device__ int            g_nm_tot[8];             // per-group nonmiss totals
__device__ long long      g_js_acc[1024];          // fixed-point per pair
__device__ int            g_cnt_acc[1024];
__device__ long long      g_ce_acc, g_r2_acc;
__device__ unsigned int   g_done, g_done2;

// ============================================================================
// Single persistent kernel: phase 1 = staging + CE + r2 partials + symmetric
// pairwise JS with direct fixed-point accumulation; grid barrier; phase 2 =
// r2 reduction (125 blocks); last-done r2 block finalizes + resets.
// ============================================================================
__global__ void __launch_bounds__(1024, 2) k_fused(
    const float4* __restrict__ logits4,   // (B, L) float4 (C=4)
    const float4* __restrict__ prob4,
    const float*  __restrict__ ytrue,     // (B, L, 5)
    const float*  __restrict__ yevo,      // (B, B)
    float*        __restrict__ out)
{
    __shared__ uint2    s_p[LC * SROW];   // 4 x fp16 clamped prob
    __shared__ unsigned s_m[LC * SROW];   // (bf16 h' << 16) | label
    __shared__ int      s_nm[8];
    __shared__ float    s_red[32];
    __shared__ float    s_j[1024];        // finalize staging
    __shared__ int      s_c[1024];
    __shared__ int      s_last;

    const int tid  = threadIdx.x;
    const int lane = tid & 31;
    const int w    = tid >> 5;
    const int bid  = blockIdx.x;
    const int l0   = bid * LC;

    if (tid < 8) s_nm[tid] = 0;
    __syncthreads();

    // ---- phase 1a: staging (coalesced; lanes walk consecutive loci) ----
    float ce_acc = 0.0f;
#pragma unroll
    for (int q = 0; q < 2; ++q) {
        int e  = q * 1024 + tid;          // 2048 = LC*32 exactly
        int i  = e >> 6;                  // batch
        int ll = e & 63;                  // local locus
        size_t gi = (size_t)i * L_ + l0 + ll;

        const float* yt = ytrue + gi * CF_;
        float lf = yt[1] + 2.0f * yt[2] + 3.0f * yt[3] + 4.0f * yt[4];
        int lbl = (int)(lf + 0.5f);

        float4 lg = logits4[gi];
        float m  = fmaxf(fmaxf(lg.x, lg.y), fmaxf(lg.z, lg.w));
        float se = __expf(lg.x - m) + __expf(lg.y - m) +
                   __expf(lg.z - m) + __expf(lg.w - m);
        if (lbl != 4) {
            float sel = (lbl == 0) ? lg.x : (lbl == 1) ? lg.y : (lbl == 2) ? lg.z : lg.w;
            ce_acc += (m + LN2F * __log2f(se)) - sel;
        }

        float4 p = prob4[gi];
        float a = fmaxf(p.x, 1e-7f), b = fmaxf(p.y, 1e-7f);
        float c = fmaxf(p.z, 1e-7f), d = fmaxf(p.w, 1e-7f);
        float hp = a * __log2f(a) + b * __log2f(b) +
                   c * __log2f(c) + d * __log2f(d) + (a + b + c + d);
        unsigned hb = (__float_as_uint(hp) + 0x8000u) & 0xFFFF0000u;

        __half2 p01 = __floats2half2_rn(a, b);
        __half2 p23 = __floats2half2_rn(c, d);
        int idx = ll * SROW + i;
        s_p[idx] = make_uint2(reinterpret_cast<unsigned&>(p01),
                              reinterpret_cast<unsigned&>(p23));
        s_m[idx] = hb | (unsigned)lbl;
    }

    // CE: warp partials -> CTA sum -> one deterministic fixed-point atomic
#pragma unroll
    for (int o = 16; o > 0; o >>= 1) ce_acc += __shfl_xor_sync(0xFFFFFFFFu, ce_acc, o);
    if (lane == 0) s_red[w] = ce_acc;
    __syncthreads();
    if (tid == 0) {
        float s = 0.0f;
#pragma unroll
        for (int k = 0; k < 32; ++k) s += s_red[k];
        atomicAdd((unsigned long long*)&g_ce_acc,
                  (unsigned long long)(long long)(s * SCALE_S));
    }

    // ---- phase 1b: r2 group partials ----
    if (tid < LC * 8) {
        int g  = tid & 7;
        int ll = tid >> 3;
        int base = ll * SROW + g * 4;
        float pred = 0.0f;
        int alt = 0, nm = 0;
#pragma unroll
        for (int q = 0; q < 4; ++q) {
            uint2 u = s_p[base + q];
            float2 f01 = __half22float2(reinterpret_cast<__half2&>(u.x));
            float2 f23 = __half22float2(reinterpret_cast<__half2&>(u.y));
            pred += f01.y + f23.x + f23.y;
            int lb = s_m[base + q] & 0xFF;
            alt += (lb >= 1 && lb <= 3);
            nm  |= (lb != 4);
        }
        int l = l0 + ll;
        g_pred[l * 8 + g] = 0.25f * pred;
        g_altp[l * 8 + g] = (unsigned char)(alt | (nm << 4));
        if (nm) atomicAdd(&s_nm[g], 1);
    }
    __syncthreads();
    if (tid < 8) atomicAdd(&g_nm_tot[tid], s_nm[tid]);

    // ---- phase 1c: symmetric pairwise JS (proven uniform loop) ----
    const int i = w;
    const int j = lane;
    const int start = (j < i) ? (LC / 2) : 0;

    float js = 0.0f;
    int   cnt = 0;
#pragma unroll 2
    for (int k = 0; k < LC / 2; ++k) {
        const int row = (start + k) * SROW;
        unsigned wi = s_m[row + i];           // broadcast
        if ((wi & 0xFFu) == 4u) continue;     // warp-uniform skip (20% of loci)
        unsigned wj = s_m[row + j];
        bool act = (((wi ^ wj) & 0xFFu) == 0u);
        float msk = act ? 1.0f : 0.0f;
        uint2 ui = s_p[row + i];              // broadcast
        uint2 uj = s_p[row + j];
        __half2 s01 = __hadd2(reinterpret_cast<__half2&>(ui.x),
                              reinterpret_cast<__half2&>(uj.x));
        __half2 s23 = __hadd2(reinterpret_cast<__half2&>(ui.y),
                              reinterpret_cast<__half2&>(uj.y));
        float2 f01 = __half22float2(s01);
        float2 f23 = __half22float2(s23);
        float slog2 = f01.x * __log2f(f01.x) + f01.y * __log2f(f01.y) +
                      f23.x * __log2f(f23.x) + f23.y * __log2f(f23.y);
        float hsum = __uint_as_float(wi & 0xFFFF0000u) +
                     __uint_as_float(wj & 0xFFFF0000u);
        js  = fmaf(msk, hsum - slog2, js);    // HLN2F applied at finalize
        cnt += act;
    }

    // direct fixed-point accumulation (order-independent => deterministic)
    atomicAdd((unsigned long long*)&g_js_acc[tid],
              (unsigned long long)(long long)(js * SCALE_JS));
    if (cnt) atomicAdd(&g_cnt_acc[tid], cnt);

    // ---- grid-wide barrier (all NB CTAs are co-resident by construction) ----
    __threadfence();
    __syncthreads();
    if (tid == 0) {
        atomicAdd(&g_done, 1u);
        while (atomicOr(&g_done, 0u) < NB) __nanosleep(64);
    }
    __syncthreads();
    __threadfence();

    // blocks >= NR2 are done
    if (bid >= NR2) return;

    // ---- phase 2: r2 reduction; 125 blocks x 1024 = 128000 items exactly ----
    {
        if (tid < 8) s_nm[tid] = g_nm_tot[tid];
        __syncthreads();
        int idx = bid * 1024 + tid;
        int g = idx & 7;
        float cntg = fmaxf(4.0f * (float)s_nm[g], 1.0f);
        unsigned char pk = g_altp[idx];
        float alt = (float)(pk & 15);
        bool nonmiss = (pk & 16) != 0;
        float af2 = nonmiss ? (alt / cntg) : 0.5f;
        float r2acc = 0.0f;
        if (nonmiss && af2 != 0.0f && af2 != 1.0f) {
            float den = fmaxf(af2 * (1.0f - af2), 0.01f);
            float dd  = g_pred[idx] - af2;
            r2acc = dd * dd / den;
        }
#pragma unroll
        for (int o = 16; o > 0; o >>= 1) r2acc += __shfl_xor_sync(0xFFFFFFFFu, r2acc, o);
        if (lane == 0) s_red[w] = r2acc;
        __syncthreads();
        if (tid == 0) {
            float r2 = 0.0f;
#pragma unroll
            for (int k = 0; k < 32; ++k) r2 += s_red[k];
            atomicAdd((unsigned long long*)&g_r2_acc,
                      (unsigned long long)(long long)(r2 * SCALE_S));
        }
    }

    // ---- completion counter among r2 blocks; last finalizes ----
    __threadfence();
    __syncthreads();
    if (tid == 0) s_last = (atomicAdd(&g_done2, 1u) == NR2 - 1);
    __syncthreads();
    if (!s_last) return;
    __threadfence();

    // evo combine: transpose symmetric halves, weights, output
    s_j[tid] = (float)((double)g_js_acc[tid] * ISCALE_JS);
    s_c[tid] = g_cnt_acc[tid];
    __syncthreads();
    const int tT = lane * 32 + w;
    float jsv = HLN2F * (s_j[tid] + s_j[tT]) /
                fmaxf((float)(s_c[tid] + s_c[tT]), 1.0f);
    float wgt = __expf(-yevo[tid]);
    float rs = wgt;
#pragma unroll
    for (int o = 16; o > 0; o >>= 1) rs += __shfl_xor_sync(0xFFFFFFFFu, rs, o);
    float term = (wgt / (rs + 1e-8f)) * jsv;
#pragma unroll
    for (int o = 16; o > 0; o >>= 1) term += __shfl_xor_sync(0xFFFFFFFFu, term, o);
    __syncthreads();
    if (lane == 0) s_red[w] = term;
    __syncthreads();
    if (tid == 0) {
        float evo = 0.0f;
#pragma unroll
        for (int k = 0; k < 32; ++k) evo += s_red[k];
        float ce = (float)((double)g_ce_acc * ISCALE_S);
        float r2 = (float)((double)g_r2_acc * ISCALE_S);
        if (!isfinite(evo)) evo = 0.0f;
        out[0] = ce - 0.125f * r2 + evo;   // r2_loss = -sum*GS/B
    }

    // reset accumulators for the next graph replay
    __syncthreads();
    g_js_acc[tid] = 0ll;
    g_cnt_acc[tid] = 0;
    if (tid < 8) g_nm_tot[tid] = 0;
    if (tid == 0) { g_ce_acc = 0ll; g_r2_acc = 0ll; g_done = 0u; g_done2 = 0u; }
}

extern "C" void kernel_launch(void* const* d_in, const int* in_sizes, int n_in,
                              void* d_out, int out_size)
{
    const float* logits = (const float*)d_in[0];
    const float* prob   = (const float*)d_in[1];
    const float* ytrue  = (const float*)d_in[2];
    const float* yevo   = (const float*)d_in[3];

    k_fused<<<NB, 1024>>>((const float4*)logits, (const float4*)prob,
                          ytrue, yevo, (float*)d_out);
}

// round 14
// speedup vs baseline: 1.3985x; 1.0198x over previous
#include <cuda_runtime.h>
#include <cuda_fp16.h>
#include <math.h>

// Problem constants (fixed by reference)
#define B_     32
#define L_     16000
#define CF_    5
#define LN2F   0.69314718055994531f
#define HLN2F  0.34657359027997264f   // 0.5*ln2

// Tiling: 56 loci per CTA -> 286 CTAs (<= 296 co-residency slots = 148 SMs x 2,
// forced by __launch_bounds__(1024,2)). Even tiles => exact symmetric split.
// Max pair-work per SM: 2 x 56 = 112 loci (vs 128 with LC=64) => better balance.
#define LC     56
#define NB     286
#define NR2    125                     // r2 blocks after barrier: 125*1024 = 128000
#define SROW   33                      // smem row stride (elements)

#define SCALE_JS   4294967296.0f       // 2^32
#define ISCALE_JS  (1.0 / 4294967296.0)
#define SCALE_S    1048576.0f          // 2^20 (ce, r2)
#define ISCALE_S   (1.0 / 1048576.0)

// ---- scratch (device globals, zero-initialized at module load) ----
__device__ float          g_pred[L_ * 8];          // [locus][group]
__device__ unsigned char  g_altp[L_ * 8];          // alt_cnt | (nonmiss<<4)
__device__ int            g_nm_tot[8];             // per-group nonmiss totals
__device__ long long      g_js_acc[1024];          // fixed-point per pair
__device__ int            g_cnt_acc[1024];
__device__ long long      g_ce_acc, g_r2_acc;
__device__ unsigned int   g_done, g_done2;

// ============================================================================
// Single persistent kernel: phase 1 = staging + CE + r2 partials + symmetric
// pairwise JS with direct fixed-point accumulation; grid barrier; phase 2 =
// r2 reduction (125 blocks); last-done r2 block finalizes + resets.
// ============================================================================
__global__ void __launch_bounds__(1024, 2) k_fused(
    const float4* __restrict__ logits4,   // (B, L) float4 (C=4)
    const float4* __restrict__ prob4,
    const float*  __restrict__ ytrue,     // (B, L, 5)
    const float*  __restrict__ yevo,      // (B, B)
    float*        __restrict__ out)
{
    __shared__ uint2    s_p[LC * SROW];   // 4 x fp16 clamped prob
    __shared__ unsigned s_m[LC * SROW];   // (bf16 h' << 16) | label
    __shared__ int      s_nm[8];
    __shared__ float    s_red[32];
    __shared__ float    s_j[1024];        // finalize staging
    __shared__ int      s_c[1024];
    __shared__ int      s_last;

    const int tid  = threadIdx.x;
    const int lane = tid & 31;
    const int w    = tid >> 5;
    const int bid  = blockIdx.x;
    const int l0   = bid * LC;
    const int nloc = min(LC, L_ - l0);     // 56 or 40 (even)
    const int n32  = nloc * 32;
    const int H    = nloc >> 1;

    if (tid < 8) s_nm[tid] = 0;
    __syncthreads();

    // ---- phase 1a: staging (coalesced; lanes walk consecutive loci) ----
    float ce_acc = 0.0f;
    for (int e = tid; e < n32; e += 1024) {
        int i  = e / nloc;                // batch
        int ll = e - i * nloc;            // local locus
        size_t gi = (size_t)i * L_ + l0 + ll;

        const float* yt = ytrue + gi * CF_;
        float lf = yt[1] + 2.0f * yt[2] + 3.0f * yt[3] + 4.0f * yt[4];
        int lbl = (int)(lf + 0.5f);

        float4 lg = logits4[gi];
        float m  = fmaxf(fmaxf(lg.x, lg.y), fmaxf(lg.z, lg.w));
        float se = __expf(lg.x - m) + __expf(lg.y - m) +
                   __expf(lg.z - m) + __expf(lg.w - m);
        if (lbl != 4) {
            float sel = (lbl == 0) ? lg.x : (lbl == 1) ? lg.y : (lbl == 2) ? lg.z : lg.w;
            ce_acc += (m + LN2F * __log2f(se)) - sel;
        }

        float4 p = prob4[gi];
        float a = fmaxf(p.x, 1e-7f), b = fmaxf(p.y, 1e-7f);
        float c = fmaxf(p.z, 1e-7f), d = fmaxf(p.w, 1e-7f);
        float hp = a * __log2f(a) + b * __log2f(b) +
                   c * __log2f(c) + d * __log2f(d) + (a + b + c + d);
        unsigned hb = (__float_as_uint(hp) + 0x8000u) & 0xFFFF0000u;

        __half2 p01 = __floats2half2_rn(a, b);
        __half2 p23 = __floats2half2_rn(c, d);
        int idx = ll * SROW + i;
        s_p[idx] = make_uint2(reinterpret_cast<unsigned&>(p01),
                              reinterpret_cast<unsigned&>(p23));
        s_m[idx] = hb | (unsigned)lbl;
    }

    // CE: warp partials -> CTA sum -> one deterministic fixed-point atomic
#pragma unroll
    for (int o = 16; o > 0; o >>= 1) ce_acc += __shfl_xor_sync(0xFFFFFFFFu, ce_acc, o);
    if (lane == 0) s_red[w] = ce_acc;
    __syncthreads();
    if (tid == 0) {
        float s = 0.0f;
#pragma unroll
        for (int k = 0; k < 32; ++k) s += s_red[k];
        atomicAdd((unsigned long long*)&g_ce_acc,
                  (unsigned long long)(long long)(s * SCALE_S));
    }

    // ---- phase 1b: r2 group partials ----
    if (tid < nloc * 8) {
        int g  = tid & 7;
        int ll = tid >> 3;
        int base = ll * SROW + g * 4;
        float pred = 0.0f;
        int alt = 0, nm = 0;
#pragma unroll
        for (int q = 0; q < 4; ++q) {
            uint2 u = s_p[base + q];
            float2 f01 = __half22float2(reinterpret_cast<__half2&>(u.x));
            float2 f23 = __half22float2(reinterpret_cast<__half2&>(u.y));
            pred += f01.y + f23.x + f23.y;
            int lb = s_m[base + q] & 0xFF;
            alt += (lb >= 1 && lb <= 3);
            nm  |= (lb != 4);
        }
        int l = l0 + ll;
        g_pred[l * 8 + g] = 0.25f * pred;
        g_altp[l * 8 + g] = (unsigned char)(alt | (nm << 4));
        if (nm) atomicAdd(&s_nm[g], 1);
    }
    __syncthreads();
    if (tid < 8) atomicAdd(&g_nm_tot[tid], s_nm[tid]);

    // ---- phase 1c: symmetric pairwise JS (proven uniform loop) ----
    const int i = w;
    const int j = lane;
    const int start = (j < i) ? H : 0;

    float js = 0.0f;
    int   cnt = 0;
#pragma unroll 2
    for (int k = 0; k < H; ++k) {
        const int row = (start + k) * SROW;
        unsigned wi = s_m[row + i];           // broadcast
        if ((wi & 0xFFu) == 4u) continue;     // warp-uniform skip (20% of loci)
        unsigned wj = s_m[row + j];
        bool act = (((wi ^ wj) & 0xFFu) == 0u);
        float msk = act ? 1.0f : 0.0f;
        uint2 ui = s_p[row + i];              // broadcast
        uint2 uj = s_p[row + j];
        __half2 s01 = __hadd2(reinterpret_cast<__half2&>(ui.x),
                              reinterpret_cast<__half2&>(uj.x));
        __half2 s23 = __hadd2(reinterpret_cast<__half2&>(ui.y),
                              reinterpret_cast<__half2&>(uj.y));
        float2 f01 = __half22float2(s01);
        float2 f23 = __half22float2(s23);
        float slog2 = f01.x * __log2f(f01.x) + f01.y * __log2f(f01.y) +
                      f23.x * __log2f(f23.x) + f23.y * __log2f(f23.y);
        float hsum = __uint_as_float(wi & 0xFFFF0000u) +
                     __uint_as_float(wj & 0xFFFF0000u);
        js  = fmaf(msk, hsum - slog2, js);    // HLN2F applied at finalize
        cnt += act;
    }

    // direct fixed-point accumulation (order-independent => deterministic)
    atomicAdd((unsigned long long*)&g_js_acc[tid],
              (unsigned long long)(long long)(js * SCALE_JS));
    if (cnt) atomicAdd(&g_cnt_acc[tid], cnt);

    // ---- grid-wide barrier (all NB CTAs are co-resident by construction) ----
    __threadfence();
    __syncthreads();
    if (tid == 0) {
        atomicAdd(&g_done, 1u);
        while (atomicOr(&g_done, 0u) < NB) __nanosleep(64);
    }
    __syncthreads();
    __threadfence();

    // blocks >= NR2 are done
    if (bid >= NR2) return;

    // ---- phase 2: r2 reduction; 125 blocks x 1024 = 128000 items exactly ----
    {
        if (tid < 8) s_nm[tid] = g_nm_tot[tid];
        __syncthreads();
        int idx = bid * 1024 + tid;
        int g = idx & 7;
        float cntg = fmaxf(4.0f * (float)s_nm[g], 1.0f);
        unsigned char pk = g_altp[idx];
        float alt = (float)(pk & 15);
        bool nonmiss = (pk & 16) != 0;
        float af2 = nonmiss ? (alt / cntg) : 0.5f;
        float r2acc = 0.0f;
        if (nonmiss && af2 != 0.0f && af2 != 1.0f) {
            float den = fmaxf(af2 * (1.0f - af2), 0.01f);
            float dd  = g_pred[idx] - af2;
            r2acc = dd * dd / den;
        }
#pragma unroll
        for (int o = 16; o > 0; o >>= 1) r2acc += __shfl_xor_sync(0xFFFFFFFFu, r2acc, o);
        if (lane == 0) s_red[w] = r2acc;
        __syncthreads();
        if (tid == 0) {
            float r2 = 0.0f;
#pragma unroll
            for (int k = 0; k < 32; ++k) r2 += s_red[k];
            atomicAdd((unsigned long long*)&g_r2_acc,
                      (unsigned long long)(long long)(r2 * SCALE_S));
        }
    }

    // ---- completion counter among r2 blocks; last finalizes ----
    __threadfence();
    __syncthreads();
    if (tid == 0) s_last = (atomicAdd(&g_done2, 1u) == NR2 - 1);
    __syncthreads();
    if (!s_last) return;
    __threadfence();

    // evo combine: transpose symmetric halves, weights, output
    s_j[tid] = (float)((double)g_js_acc[tid] * ISCALE_JS);
    s_c[tid] = g_cnt_acc[tid];
    __syncthreads();
    const int tT = lane * 32 + w;
    float jsv = HLN2F * (s_j[tid] + s_j[tT]) /
                fmaxf((float)(s_c[tid] + s_c[tT]), 1.0f);
    float wgt = __expf(-yevo[tid]);
    float rs = wgt;
#pragma unroll
    for (int o = 16; o > 0; o >>= 1) rs += __shfl_xor_sync(0xFFFFFFFFu, rs, o);
    float term = (wgt / (rs + 1e-8f)) * jsv;
#pragma unroll
    for (int o = 16; o > 0; o >>= 1) term += __shfl_xor_sync(0xFFFFFFFFu, term, o);
    __syncthreads();
    if (lane == 0) s_red[w] = term;
    __syncthreads();
    if (tid == 0) {
        float evo = 0.0f;
#pragma unroll
        for (int k = 0; k < 32; ++k) evo += s_red[k];
        float ce = (float)((double)g_ce_acc * ISCALE_S);
        float r2 = (float)((double)g_r2_acc * ISCALE_S);
        if (!isfinite(evo)) evo = 0.0f;
        out[0] = ce - 0.125f * r2 + evo;   // r2_loss = -sum*GS/B
    }

    // reset accumulators for the next graph replay
    __syncthreads();
    g_js_acc[tid] = 0ll;
    g_cnt_acc[tid] = 0;
    if (tid < 8) g_nm_tot[tid] = 0;
    if (tid == 0) { g_ce_acc = 0ll; g_r2_acc = 0ll; g_done = 0u; g_done2 = 0u; }
}

extern "C" void kernel_launch(void* const* d_in, const int* in_sizes, int n_in,
                              void* d_out, int out_size)
{
    const float* logits = (const float*)d_in[0];
    const float* prob   = (const float*)d_in[1];
    const float* ytrue  = (const float*)d_in[2];
    const float* yevo   = (const float*)d_in[3];

    k_fused<<<NB, 1024>>>((const float4*)logits, (const float4*)prob,
                          ytrue, yevo, (float*)d_out);
}